// round 6
// baseline (speedup 1.0000x reference)
#include <cuda_runtime.h>
#include <cstdint>

#define B_    4096
#define H_    512
#define TOBS  30
#define TPRED 60

// ------------------ device scratch (static, no runtime alloc) ------------------
__device__ float g_h0[2][B_ * H_];
__device__ float g_h1[2][B_ * H_];
__device__ float g_hd[2][B_ * H_];
// tf32-pre-rounded images of h (A operand for MMA; no in-loop cvt needed)
__device__ float g_h0r[2][B_ * H_];
__device__ float g_h1r[2][B_ * H_];
__device__ float g_hdr[2][B_ * H_];
__device__ float g_decin[2][B_ * 2];
// packed fragment-interleaved weights: [kb<64][g<3][jb<64][lane<32][v<2]
// value = tf32(W[g*512 + jb*8 + lane/4][kb*8 + lane%4 + 4*v])
__device__ float g_Wp[4][786432];   // {W_hh0, W_ih1, W_hh1, W_hhd}
// combined bias table per layer: [j][4] = {bih_r+bhh_r, bih_z+bhh_z, bih_n, bhh_n}
__device__ float g_b4[3][H_ * 4];

// smem: A bufs 2 x (128x68 f32 = 34816B), B bufs 2 x (192*256B = 49152B)
#define SMA_BYTES 34816
#define SMB_BYTES 49152
#define SMB_OFF   (2 * SMA_BYTES)
#define SMEM_BYTES (2 * SMA_BYTES + 2 * SMB_BYTES)   // 167936

// ------------------ helpers ------------------
__device__ __forceinline__ float tf32r(float x) {
    uint32_t u;
    asm("cvt.rna.tf32.f32 %0, %1;" : "=r"(u) : "f"(x));
    return __uint_as_float(u);
}
__device__ __forceinline__ void mma8(float c[4], uint32_t a0, uint32_t a1, uint32_t a2, uint32_t a3,
                                     uint32_t b0, uint32_t b1) {
    asm volatile(
        "mma.sync.aligned.m16n8k8.row.col.f32.tf32.tf32.f32 "
        "{%0,%1,%2,%3},{%4,%5,%6,%7},{%8,%9},{%0,%1,%2,%3};"
        : "+f"(c[0]), "+f"(c[1]), "+f"(c[2]), "+f"(c[3])
        : "r"(a0), "r"(a1), "r"(a2), "r"(a3), "r"(b0), "r"(b1));
}
__device__ __forceinline__ void cpasync16(uint32_t dst, const void* src) {
    asm volatile("cp.async.cg.shared.global [%0], [%1], 16;" :: "r"(dst), "l"(src));
}
__device__ __forceinline__ float sigf(float v) { return 1.0f / (1.0f + __expf(-v)); }

// ------------------ prep: pack weights (tf32-rounded) + combined biases ------------------
__global__ void prep_kernel(const float* __restrict__ Whh0, const float* __restrict__ Wih1,
                            const float* __restrict__ Whh1, const float* __restrict__ Whhd,
                            const float* __restrict__ bih0, const float* __restrict__ bhh0,
                            const float* __restrict__ bih1, const float* __restrict__ bhh1,
                            const float* __restrict__ bihd, const float* __restrict__ bhhd) {
    const int NW = 4 * 786432;
    const int total = NW + 3 * 2048;
    for (int idx = blockIdx.x * blockDim.x + threadIdx.x; idx < total;
         idx += gridDim.x * blockDim.x) {
        if (idx < NW) {
            int mat = idx / 786432, o = idx % 786432;
            int kb = o / 12288, rem = o % 12288;
            int g = rem / 4096, rem2 = rem % 4096;
            int jb = rem2 / 64, l2 = rem2 % 64;
            int lane = l2 >> 1, v = l2 & 1;
            int row = g * 512 + jb * 8 + (lane >> 2);
            int k = kb * 8 + (lane & 3) + 4 * v;
            const float* Wsrc = (mat == 0) ? Whh0 : (mat == 1) ? Wih1 : (mat == 2) ? Whh1 : Whhd;
            g_Wp[mat][o] = tf32r(Wsrc[row * 512 + k]);
        } else {
            int r = idx - NW;
            int l = r / 2048, rem = r % 2048;
            int j = rem >> 2, s = rem & 3;
            const float* bi = (l == 0) ? bih0 : (l == 1) ? bih1 : bihd;
            const float* bh = (l == 0) ? bhh0 : (l == 1) ? bhh1 : bhhd;
            float v;
            if (s == 0)      v = bi[j] + bh[j];
            else if (s == 1) v = bi[512 + j] + bh[512 + j];
            else if (s == 2) v = bi[1024 + j];
            else             v = bh[1024 + j];
            g_b4[l][j * 4 + s] = v;
        }
    }
}

__global__ void init_kernel(const float* __restrict__ x) {
    int idx0 = blockIdx.x * blockDim.x + threadIdx.x;
    for (int i = idx0; i < B_ * H_; i += gridDim.x * blockDim.x) {
        g_h0[0][i] = 0.0f;  g_h1[0][i] = 0.0f;
        g_h0r[0][i] = 0.0f; g_h1r[0][i] = 0.0f;
    }
    if (idx0 < B_ * 2) {
        int m = idx0 >> 1, o = idx0 & 1;
        g_decin[0][idx0] = x[m * 120 + 116 + o];  // x[m][29][o]
    }
}

// ------------------ fused GRU step: smem-staged A and B, 16 warps ------------------
// MODE 0: layer0 (x K=4 scalar ih, tensor hh). MODE 1: layer1 (tensor ih + hh, 2 passes).
// MODE 2: decoder (decin K=2 scalar ih, tensor hh).
template <int MODE>
__global__ void __launch_bounds__(512, 1)
gru_step(int t, const float* __restrict__ x, const float* __restrict__ Wraw) {
    extern __shared__ char smem[];
    uint32_t sb = (uint32_t)__cvta_generic_to_shared(smem);
    const int tid = threadIdx.x, lane = tid & 31, w = tid >> 5;
    const int wm = w & 3, wn = w >> 2;            // 4 M-warps x 4 N-warps
    const int m0 = blockIdx.x * 128, n0 = blockIdx.y * 64;
    const int jb_base = blockIdx.y * 8;

    const float *Aimg0, *Aimg1 = nullptr, *Wp0, *Wp1 = nullptr;
    const float *hin, *b4p, *xsm = nullptr;
    float *hout, *houtr;
    if constexpr (MODE == 0) {
        Aimg0 = g_h0r[t & 1]; Wp0 = g_Wp[0];
        hin = g_h0[t & 1]; hout = g_h0[(t + 1) & 1]; houtr = g_h0r[(t + 1) & 1];
        b4p = g_b4[0];
    } else if constexpr (MODE == 1) {
        Aimg0 = g_h0r[(t + 1) & 1]; Wp0 = g_Wp[1];   // gi pass (x = new h0)
        Aimg1 = g_h1r[t & 1];       Wp1 = g_Wp[2];   // gh pass
        hin = g_h1[t & 1]; hout = g_h1[(t + 1) & 1]; houtr = g_h1r[(t + 1) & 1];
        b4p = g_b4[1];
    } else {
        Aimg0 = (t == 0) ? g_h1r[0] : g_hdr[t & 1]; Wp0 = g_Wp[3];
        hin = (t == 0) ? g_h1[0] : g_hd[t & 1];
        hout = g_hd[(t + 1) & 1]; houtr = g_hdr[(t + 1) & 1];
        b4p = g_b4[2]; xsm = g_decin[t & 1];
    }

    constexpr int SETS = (MODE == 1) ? 4 : 3;
    float acc[SETS][2][2][4];
#pragma unroll
    for (int s = 0; s < SETS; ++s)
#pragma unroll
        for (int mf = 0; mf < 2; ++mf)
#pragma unroll
            for (int nf = 0; nf < 2; ++nf)
#pragma unroll
                for (int q = 0; q < 4; ++q) acc[s][mf][nf][q] = 0.0f;

    // chunk loader: A 128x64 f32 (pitch 68) + B 192 fragment-blocks of 256B
    auto load_chunk = [&](int cg) {
        const int b = cg & 1, pass = cg >> 3, c = cg & 7;
        const float* A = (MODE == 1 && pass) ? Aimg1 : Aimg0;
        const float* W = (MODE == 1 && pass) ? Wp1 : Wp0;
        const uint32_t abase = sb + b * SMA_BYTES;
        const uint32_t bbase = sb + SMB_OFF + b * SMB_BYTES;
#pragma unroll
        for (int i = 0; i < 4; ++i) {
            int u = tid + i * 512;
            int row = u >> 4, c4 = (u & 15) << 2;
            cpasync16(abase + (uint32_t)((row * 68 + c4) * 4),
                      A + (m0 + row) * 512 + c * 64 + c4);
        }
#pragma unroll
        for (int i = 0; i < 6; ++i) {
            int u = tid + i * 512;
            int blk = u >> 4, q = u & 15;
            int k8 = blk / 24, r24 = blk % 24;
            int g = r24 >> 3, jb = r24 & 7;
            cpasync16(bbase + (uint32_t)(blk * 256 + q * 16),
                      W + (c * 8 + k8) * 12288 + g * 4096 + (jb_base + jb) * 64 + q * 4);
        }
        asm volatile("cp.async.commit_group;" ::: "memory");
    };

    constexpr int NCH = (MODE == 1) ? 16 : 8;
    load_chunk(0);
    for (int cg = 0; cg < NCH; ++cg) {
        asm volatile("cp.async.wait_group 0;" ::: "memory");
        __syncthreads();
        if (cg + 1 < NCH) load_chunk(cg + 1);
        const int b = cg & 1, pass = cg >> 3, c = cg & 7;
        const float (*sC)[68] = reinterpret_cast<const float(*)[68]>(smem + b * SMA_BYTES);
        const float* sB = reinterpret_cast<const float*>(smem + SMB_OFF + b * SMB_BYTES);
#pragma unroll
        for (int ks = 0; ks < 8; ++ks) {
            const int kk = ks * 8 + (lane & 3);
            uint32_t a[2][4];
#pragma unroll
            for (int mf = 0; mf < 2; ++mf) {
                int rb = wm * 32 + mf * 16 + (lane >> 2);
                a[mf][0] = __float_as_uint(sC[rb][kk]);
                a[mf][1] = __float_as_uint(sC[rb + 8][kk]);
                a[mf][2] = __float_as_uint(sC[rb][kk + 4]);
                a[mf][3] = __float_as_uint(sC[rb + 8][kk + 4]);
            }
            const float* bp = sB + (ks * 24) * 64 + lane * 2;
#pragma unroll
            for (int g = 0; g < 3; ++g) {
                int s;
                bool first;
                if (g < 2) { s = g; first = (cg == 0 && ks == 0); }
                else {
                    s = (MODE == 1) ? (2 + pass) : 2;
                    first = (c == 0 && ks == 0);
                }
#pragma unroll
                for (int nf = 0; nf < 2; ++nf) {
                    const float2 bv = *reinterpret_cast<const float2*>(
                        bp + (g * 8 + wn * 2 + nf) * 64);
                    uint32_t b0 = __float_as_uint(bv.x), b1 = __float_as_uint(bv.y);
                    if (first) {
#pragma unroll
                        for (int q = 0; q < 4; ++q) { acc[s][0][nf][q] = 0.0f; acc[s][1][nf][q] = 0.0f; }
                    }
                    mma8(acc[s][0][nf], a[0][0], a[0][1], a[0][2], a[0][3], b0, b1);
                    mma8(acc[s][1][nf], a[1][0], a[1][1], a[1][2], a[1][3], b0, b1);
                }
            }
        }
    }

    // ------------- epilogue: gates + h update -------------
#pragma unroll
    for (int mf = 0; mf < 2; ++mf) {
#pragma unroll
        for (int rr = 0; rr < 2; ++rr) {
            int m = m0 + wm * 32 + mf * 16 + rr * 8 + (lane >> 2);
            float4 xr = make_float4(0.f, 0.f, 0.f, 0.f);
            float2 x2 = make_float2(0.f, 0.f);
            if constexpr (MODE == 0) xr = *reinterpret_cast<const float4*>(&x[m * 120 + t * 4]);
            if constexpr (MODE == 2) x2 = *reinterpret_cast<const float2*>(&xsm[m * 2]);
#pragma unroll
            for (int nf = 0; nf < 2; ++nf) {
                int j = n0 + wn * 16 + nf * 8 + (lane & 3) * 2;
                float2 ho = *reinterpret_cast<const float2*>(&hin[m * 512 + j]);
                float hnew[2];
#pragma unroll
                for (int cc = 0; cc < 2; ++cc) {
                    int jj = j + cc;
                    float4 bb = *reinterpret_cast<const float4*>(&b4p[jj * 4]);
                    int q = rr * 2 + cc;
                    float vr = acc[0][mf][nf][q];
                    float vz = acc[1][mf][nf][q];
                    float gir = 0.f, giz = 0.f, gin = 0.f;
                    if constexpr (MODE == 0) {
                        float4 wr = *reinterpret_cast<const float4*>(&Wraw[jj * 4]);
                        float4 wz = *reinterpret_cast<const float4*>(&Wraw[(jj + 512) * 4]);
                        float4 wn4 = *reinterpret_cast<const float4*>(&Wraw[(jj + 1024) * 4]);
                        gir = xr.x * wr.x + xr.y * wr.y + xr.z * wr.z + xr.w * wr.w;
                        giz = xr.x * wz.x + xr.y * wz.y + xr.z * wz.z + xr.w * wz.w;
                        gin = xr.x * wn4.x + xr.y * wn4.y + xr.z * wn4.z + xr.w * wn4.w;
                    } else if constexpr (MODE == 2) {
                        float2 wr = *reinterpret_cast<const float2*>(&Wraw[jj * 2]);
                        float2 wz = *reinterpret_cast<const float2*>(&Wraw[(jj + 512) * 2]);
                        float2 wn2 = *reinterpret_cast<const float2*>(&Wraw[(jj + 1024) * 2]);
                        gir = x2.x * wr.x + x2.y * wr.y;
                        giz = x2.x * wz.x + x2.y * wz.y;
                        gin = x2.x * wn2.x + x2.y * wn2.y;
                    }
                    float rg = sigf(vr + gir + bb.x);
                    float zg = sigf(vz + giz + bb.y);
                    float in_term, hn_term;
                    if constexpr (MODE == 1) {
                        in_term = acc[2][mf][nf][q] + bb.z;
                        hn_term = acc[3][mf][nf][q] + bb.w;
                    } else {
                        in_term = gin + bb.z;
                        hn_term = acc[2][mf][nf][q] + bb.w;
                    }
                    float ng = tanhf(in_term + rg * hn_term);
                    float hprev = cc ? ho.y : ho.x;
                    hnew[cc] = (1.0f - zg) * ng + zg * hprev;
                }
                *reinterpret_cast<float2*>(&hout[m * 512 + j]) = make_float2(hnew[0], hnew[1]);
                *reinterpret_cast<float2*>(&houtr[m * 512 + j]) =
                    make_float2(tf32r(hnew[0]), tf32r(hnew[1]));
            }
        }
    }
}

// ------------------ decoder FC: pred = h @ W_fc.T + b_fc; feed back ------------------
__global__ void fc_kernel(int td, const float* __restrict__ Wfc, const float* __restrict__ bfc,
                          float* __restrict__ out) {
    int gw = (blockIdx.x * blockDim.x + threadIdx.x) >> 5;  // one warp per batch row
    int lane = threadIdx.x & 31;
    if (gw >= B_) return;
    const float* h = g_hd[(td + 1) & 1] + gw * 512;
    float s0 = 0.f, s1 = 0.f;
#pragma unroll
    for (int i = 0; i < 16; ++i) {
        float hv = h[lane + 32 * i];
        s0 += hv * Wfc[lane + 32 * i];
        s1 += hv * Wfc[512 + lane + 32 * i];
    }
#pragma unroll
    for (int o = 16; o; o >>= 1) {
        s0 += __shfl_xor_sync(0xffffffffu, s0, o);
        s1 += __shfl_xor_sync(0xffffffffu, s1, o);
    }
    if (lane == 0) {
        s0 += bfc[0]; s1 += bfc[1];
        out[gw * 120 + td * 2] = s0;
        out[gw * 120 + td * 2 + 1] = s1;
        float* dn = g_decin[(td + 1) & 1];
        dn[gw * 2] = s0;
        dn[gw * 2 + 1] = s1;
    }
}

// ------------------ launch ------------------
extern "C" void kernel_launch(void* const* d_in, const int* in_sizes, int n_in,
                              void* d_out, int out_size) {
    (void)in_sizes; (void)n_in; (void)out_size;
    const float* x    = (const float*)d_in[0];
    const float* Wih0 = (const float*)d_in[1];
    const float* Whh0 = (const float*)d_in[2];
    const float* bih0 = (const float*)d_in[3];
    const float* bhh0 = (const float*)d_in[4];
    const float* Wih1 = (const float*)d_in[5];
    const float* Whh1 = (const float*)d_in[6];
    const float* bih1 = (const float*)d_in[7];
    const float* bhh1 = (const float*)d_in[8];
    const float* Wihd = (const float*)d_in[9];
    const float* Whhd = (const float*)d_in[10];
    const float* bihd = (const float*)d_in[11];
    const float* bhhd = (const float*)d_in[12];
    const float* Wfc  = (const float*)d_in[13];
    const float* bfc  = (const float*)d_in[14];
    float* out = (float*)d_out;

    cudaFuncSetAttribute(gru_step<0>, cudaFuncAttributeMaxDynamicSharedMemorySize, SMEM_BYTES);
    cudaFuncSetAttribute(gru_step<1>, cudaFuncAttributeMaxDynamicSharedMemorySize, SMEM_BYTES);
    cudaFuncSetAttribute(gru_step<2>, cudaFuncAttributeMaxDynamicSharedMemorySize, SMEM_BYTES);

    prep_kernel<<<1024, 256>>>(Whh0, Wih1, Whh1, Whhd,
                               bih0, bhh0, bih1, bhh1, bihd, bhhd);
    init_kernel<<<2048, 256>>>(x);

    dim3 grid(32, 8);  // 4096/128 x 512/64
    for (int t = 0; t < TOBS; ++t) {
        gru_step<0><<<grid, 512, SMEM_BYTES>>>(t, x, Wih0);
        gru_step<1><<<grid, 512, SMEM_BYTES>>>(t, x, (const float*)nullptr);
    }
    for (int td = 0; td < TPRED; ++td) {
        gru_step<2><<<grid, 512, SMEM_BYTES>>>(td, nullptr, Wihd);
        fc_kernel<<<512, 256>>>(td, Wfc, bfc, out);
    }
}

// round 7
// speedup vs baseline: 1.3784x; 1.3784x over previous
#include <cuda_runtime.h>
#include <cuda_fp16.h>
#include <cstdint>

#define B_    4096
#define H_    512
#define TOBS  30
#define TPRED 60

// ------------------ device scratch (static, no runtime alloc) ------------------
__device__ float g_h0[2][B_ * H_];
__device__ float g_h1[2][B_ * H_];
__device__ float g_hd[2][B_ * H_];
// fp16 images of h (A operand for MMA)
__device__ __half g_h0h[2][B_ * H_];
__device__ __half g_h1h[2][B_ * H_];
__device__ __half g_hdh[2][B_ * H_];
__device__ float g_decin[2][B_ * 2];
// packed fp16 fragment-interleaved weights:
// [kb16<32][g<3][jb<64][lane<32][v<2] u32 = pack(W[row][k0], W[row][k0+1])
// row = g*512 + jb*8 + lane/4, k0 = kb16*16 + 2*(lane%4) + 8*v
__device__ uint32_t g_Wp[4][393216];   // {W_hh0, W_ih1, W_hh1, W_hhd}
// combined bias table per layer: [j][4] = {bih_r+bhh_r, bih_z+bhh_z, bih_n, bhh_n}
__device__ float g_b4[3][H_ * 4];

// smem: A bufs 2 x (128 x 72 halves = 18432B), B bufs 2 x (96 blocks x 256B = 24576B)
#define SMA_BYTES 18432
#define SMB_BYTES 24576
#define SMB_OFF   (2 * SMA_BYTES)
#define SMEM_BYTES (2 * SMA_BYTES + 2 * SMB_BYTES)   // 86016

// ------------------ helpers ------------------
__device__ __forceinline__ void mma16(float c[4], uint32_t a0, uint32_t a1, uint32_t a2,
                                      uint32_t a3, uint32_t b0, uint32_t b1) {
    asm volatile(
        "mma.sync.aligned.m16n8k16.row.col.f32.f16.f16.f32 "
        "{%0,%1,%2,%3},{%4,%5,%6,%7},{%8,%9},{%0,%1,%2,%3};"
        : "+f"(c[0]), "+f"(c[1]), "+f"(c[2]), "+f"(c[3])
        : "r"(a0), "r"(a1), "r"(a2), "r"(a3), "r"(b0), "r"(b1));
}
__device__ __forceinline__ void cpasync16(uint32_t dst, const void* src) {
    asm volatile("cp.async.cg.shared.global [%0], [%1], 16;" :: "r"(dst), "l"(src));
}
__device__ __forceinline__ float sigf(float v) { return 1.0f / (1.0f + __expf(-v)); }

// ------------------ prep: pack fp16 weights + combined biases ------------------
__global__ void prep_kernel(const float* __restrict__ Whh0, const float* __restrict__ Wih1,
                            const float* __restrict__ Whh1, const float* __restrict__ Whhd,
                            const float* __restrict__ bih0, const float* __restrict__ bhh0,
                            const float* __restrict__ bih1, const float* __restrict__ bhh1,
                            const float* __restrict__ bihd, const float* __restrict__ bhhd) {
    const int NW = 4 * 393216;
    const int total = NW + 3 * 2048;
    for (int idx = blockIdx.x * blockDim.x + threadIdx.x; idx < total;
         idx += gridDim.x * blockDim.x) {
        if (idx < NW) {
            int mat = idx / 393216, o = idx % 393216;
            int kb = o / 12288, rem = o % 12288;
            int g = rem / 4096, rem2 = rem % 4096;
            int jb = rem2 / 64, l2 = rem2 % 64;
            int lane = l2 >> 1, v = l2 & 1;
            int row = g * 512 + jb * 8 + (lane >> 2);
            int k0 = kb * 16 + 2 * (lane & 3) + 8 * v;
            const float* Wsrc = (mat == 0) ? Whh0 : (mat == 1) ? Wih1 : (mat == 2) ? Whh1 : Whhd;
            __half2 hv = __floats2half2_rn(Wsrc[row * 512 + k0], Wsrc[row * 512 + k0 + 1]);
            g_Wp[mat][o] = *reinterpret_cast<uint32_t*>(&hv);
        } else {
            int r = idx - NW;
            int l = r / 2048, rem = r % 2048;
            int j = rem >> 2, s = rem & 3;
            const float* bi = (l == 0) ? bih0 : (l == 1) ? bih1 : bihd;
            const float* bh = (l == 0) ? bhh0 : (l == 1) ? bhh1 : bhhd;
            float v;
            if (s == 0)      v = bi[j] + bh[j];
            else if (s == 1) v = bi[512 + j] + bh[512 + j];
            else if (s == 2) v = bi[1024 + j];
            else             v = bh[1024 + j];
            g_b4[l][j * 4 + s] = v;
        }
    }
}

__global__ void init_kernel(const float* __restrict__ x) {
    int idx0 = blockIdx.x * blockDim.x + threadIdx.x;
    for (int i = idx0; i < B_ * H_; i += gridDim.x * blockDim.x) {
        g_h0[0][i] = 0.0f;  g_h1[0][i] = 0.0f;
        g_h0h[0][i] = __float2half(0.0f);
        g_h1h[0][i] = __float2half(0.0f);
    }
    if (idx0 < B_ * 2) {
        int m = idx0 >> 1, o = idx0 & 1;
        g_decin[0][idx0] = x[m * 120 + 116 + o];  // x[m][29][o]
    }
}

// ------------------ fused GRU step: fp16 m16n8k16, smem-staged A and B ------------------
// MODE 0: layer0 (x K=4 scalar ih, tensor hh). MODE 1: layer1 (tensor ih + hh, 2 passes).
// MODE 2: decoder (decin K=2 scalar ih, tensor hh).
template <int MODE>
__global__ void __launch_bounds__(512, 1)
gru_step(int t, const float* __restrict__ x, const float* __restrict__ Wraw) {
    extern __shared__ char smem[];
    uint32_t sb = (uint32_t)__cvta_generic_to_shared(smem);
    const int tid = threadIdx.x, lane = tid & 31, w = tid >> 5;
    const int wm = w & 3, wn = w >> 2;            // 4 M-warps x 4 N-warps
    const int m0 = blockIdx.x * 128, n0 = blockIdx.y * 64;
    const int jb_base = blockIdx.y * 8;

    const __half *Aimg0, *Aimg1 = nullptr;
    const uint32_t *Wp0, *Wp1 = nullptr;
    const float *hin, *b4p, *xsm = nullptr;
    float* hout;
    __half* himg;
    if constexpr (MODE == 0) {
        Aimg0 = g_h0h[t & 1]; Wp0 = g_Wp[0];
        hin = g_h0[t & 1]; hout = g_h0[(t + 1) & 1]; himg = g_h0h[(t + 1) & 1];
        b4p = g_b4[0];
    } else if constexpr (MODE == 1) {
        Aimg0 = g_h0h[(t + 1) & 1]; Wp0 = g_Wp[1];   // gi pass (x = new h0)
        Aimg1 = g_h1h[t & 1];       Wp1 = g_Wp[2];   // gh pass
        hin = g_h1[t & 1]; hout = g_h1[(t + 1) & 1]; himg = g_h1h[(t + 1) & 1];
        b4p = g_b4[1];
    } else {
        Aimg0 = (t == 0) ? g_h1h[0] : g_hdh[t & 1]; Wp0 = g_Wp[3];
        hin = (t == 0) ? g_h1[0] : g_hd[t & 1];
        hout = g_hd[(t + 1) & 1]; himg = g_hdh[(t + 1) & 1];
        b4p = g_b4[2]; xsm = g_decin[t & 1];
    }

    constexpr int SETS = (MODE == 1) ? 4 : 3;
    float acc[SETS][2][2][4];
#pragma unroll
    for (int s = 0; s < SETS; ++s)
#pragma unroll
        for (int mf = 0; mf < 2; ++mf)
#pragma unroll
            for (int nf = 0; nf < 2; ++nf)
#pragma unroll
                for (int q = 0; q < 4; ++q) acc[s][mf][nf][q] = 0.0f;

    // chunk loader: A 128x64 fp16 (pitch 72 halves) + B 96 fragment-blocks of 256B
    auto load_chunk = [&](int cg) {
        const int b = cg & 1, pass = cg >> 3, c = cg & 7;
        const __half* A = (MODE == 1 && pass) ? Aimg1 : Aimg0;
        const uint32_t* W = (MODE == 1 && pass) ? Wp1 : Wp0;
        const uint32_t abase = sb + b * SMA_BYTES;
        const uint32_t bbase = sb + SMB_OFF + b * SMB_BYTES;
#pragma unroll
        for (int i = 0; i < 2; ++i) {
            int u = tid + i * 512;
            int row = u >> 3, c8 = (u & 7) << 3;
            cpasync16(abase + (uint32_t)((row * 72 + c8) * 2),
                      A + (m0 + row) * 512 + c * 64 + c8);
        }
#pragma unroll
        for (int i = 0; i < 3; ++i) {
            int u = tid + i * 512;
            int blk = u >> 4, q = u & 15;
            int ks = blk / 24, r24 = blk % 24;
            int g = r24 >> 3, jb = r24 & 7;
            cpasync16(bbase + (uint32_t)(blk * 256 + q * 16),
                      W + (c * 4 + ks) * 12288 + g * 4096 + (jb_base + jb) * 64 + q * 4);
        }
        asm volatile("cp.async.commit_group;" ::: "memory");
    };

    constexpr int NCH = (MODE == 1) ? 16 : 8;
    load_chunk(0);
    for (int cg = 0; cg < NCH; ++cg) {
        asm volatile("cp.async.wait_group 0;" ::: "memory");
        __syncthreads();
        if (cg + 1 < NCH) load_chunk(cg + 1);
        const int b = cg & 1, pass = cg >> 3, c = cg & 7;
        const __half* sA = reinterpret_cast<const __half*>(smem + b * SMA_BYTES);
        const uint32_t* sB = reinterpret_cast<const uint32_t*>(smem + SMB_OFF + b * SMB_BYTES);
#pragma unroll
        for (int ks = 0; ks < 4; ++ks) {   // 4 x k16 per 64-col chunk
            const int kc = ks * 16 + 2 * (lane & 3);
            uint32_t a[2][4];
#pragma unroll
            for (int mf = 0; mf < 2; ++mf) {
                int rb = wm * 32 + mf * 16 + (lane >> 2);
                a[mf][0] = *reinterpret_cast<const uint32_t*>(&sA[rb * 72 + kc]);
                a[mf][1] = *reinterpret_cast<const uint32_t*>(&sA[(rb + 8) * 72 + kc]);
                a[mf][2] = *reinterpret_cast<const uint32_t*>(&sA[rb * 72 + kc + 8]);
                a[mf][3] = *reinterpret_cast<const uint32_t*>(&sA[(rb + 8) * 72 + kc + 8]);
            }
            const uint32_t* bp = sB + (ks * 24) * 64 + lane * 2;
#pragma unroll
            for (int g = 0; g < 3; ++g) {
                int s;
                bool first;
                if (g < 2) { s = g; first = (cg == 0 && ks == 0); }
                else {
                    s = (MODE == 1) ? (2 + pass) : 2;
                    first = (c == 0 && ks == 0);
                }
#pragma unroll
                for (int nf = 0; nf < 2; ++nf) {
                    const uint2 bv = *reinterpret_cast<const uint2*>(
                        bp + (g * 8 + wn * 2 + nf) * 64);
                    if (first) {
#pragma unroll
                        for (int q = 0; q < 4; ++q) { acc[s][0][nf][q] = 0.0f; acc[s][1][nf][q] = 0.0f; }
                    }
                    mma16(acc[s][0][nf], a[0][0], a[0][1], a[0][2], a[0][3], bv.x, bv.y);
                    mma16(acc[s][1][nf], a[1][0], a[1][1], a[1][2], a[1][3], bv.x, bv.y);
                }
            }
        }
    }

    // ------------- epilogue: gates + h update -------------
#pragma unroll
    for (int mf = 0; mf < 2; ++mf) {
#pragma unroll
        for (int rr = 0; rr < 2; ++rr) {
            int m = m0 + wm * 32 + mf * 16 + rr * 8 + (lane >> 2);
            float4 xr = make_float4(0.f, 0.f, 0.f, 0.f);
            float2 x2 = make_float2(0.f, 0.f);
            if constexpr (MODE == 0) xr = *reinterpret_cast<const float4*>(&x[m * 120 + t * 4]);
            if constexpr (MODE == 2) x2 = *reinterpret_cast<const float2*>(&xsm[m * 2]);
#pragma unroll
            for (int nf = 0; nf < 2; ++nf) {
                int j = n0 + wn * 16 + nf * 8 + (lane & 3) * 2;
                float2 ho = *reinterpret_cast<const float2*>(&hin[m * 512 + j]);
                float hnew[2];
#pragma unroll
                for (int cc = 0; cc < 2; ++cc) {
                    int jj = j + cc;
                    float4 bb = *reinterpret_cast<const float4*>(&b4p[jj * 4]);
                    int q = rr * 2 + cc;
                    float vr = acc[0][mf][nf][q];
                    float vz = acc[1][mf][nf][q];
                    float gir = 0.f, giz = 0.f, gin = 0.f;
                    if constexpr (MODE == 0) {
                        float4 wr = *reinterpret_cast<const float4*>(&Wraw[jj * 4]);
                        float4 wz = *reinterpret_cast<const float4*>(&Wraw[(jj + 512) * 4]);
                        float4 wn4 = *reinterpret_cast<const float4*>(&Wraw[(jj + 1024) * 4]);
                        gir = xr.x * wr.x + xr.y * wr.y + xr.z * wr.z + xr.w * wr.w;
                        giz = xr.x * wz.x + xr.y * wz.y + xr.z * wz.z + xr.w * wz.w;
                        gin = xr.x * wn4.x + xr.y * wn4.y + xr.z * wn4.z + xr.w * wn4.w;
                    } else if constexpr (MODE == 2) {
                        float2 wr = *reinterpret_cast<const float2*>(&Wraw[jj * 2]);
                        float2 wz = *reinterpret_cast<const float2*>(&Wraw[(jj + 512) * 2]);
                        float2 wn2 = *reinterpret_cast<const float2*>(&Wraw[(jj + 1024) * 2]);
                        gir = x2.x * wr.x + x2.y * wr.y;
                        giz = x2.x * wz.x + x2.y * wz.y;
                        gin = x2.x * wn2.x + x2.y * wn2.y;
                    }
                    float rg = sigf(vr + gir + bb.x);
                    float zg = sigf(vz + giz + bb.y);
                    float in_term, hn_term;
                    if constexpr (MODE == 1) {
                        in_term = acc[2][mf][nf][q] + bb.z;
                        hn_term = acc[3][mf][nf][q] + bb.w;
                    } else {
                        in_term = gin + bb.z;
                        hn_term = acc[2][mf][nf][q] + bb.w;
                    }
                    float ng = tanhf(in_term + rg * hn_term);
                    float hprev = cc ? ho.y : ho.x;
                    hnew[cc] = (1.0f - zg) * ng + zg * hprev;
                }
                *reinterpret_cast<float2*>(&hout[m * 512 + j]) = make_float2(hnew[0], hnew[1]);
                __half2 hh = __floats2half2_rn(hnew[0], hnew[1]);
                *reinterpret_cast<__half2*>(&himg[m * 512 + j]) = hh;
            }
        }
    }
}

// ------------------ decoder FC: pred = h @ W_fc.T + b_fc; feed back ------------------
__global__ void fc_kernel(int td, const float* __restrict__ Wfc, const float* __restrict__ bfc,
                          float* __restrict__ out) {
    int gw = (blockIdx.x * blockDim.x + threadIdx.x) >> 5;  // one warp per batch row
    int lane = threadIdx.x & 31;
    if (gw >= B_) return;
    const float* h = g_hd[(td + 1) & 1] + gw * 512;
    float s0 = 0.f, s1 = 0.f;
#pragma unroll
    for (int i = 0; i < 16; ++i) {
        float hv = h[lane + 32 * i];
        s0 += hv * Wfc[lane + 32 * i];
        s1 += hv * Wfc[512 + lane + 32 * i];
    }
#pragma unroll
    for (int o = 16; o; o >>= 1) {
        s0 += __shfl_xor_sync(0xffffffffu, s0, o);
        s1 += __shfl_xor_sync(0xffffffffu, s1, o);
    }
    if (lane == 0) {
        s0 += bfc[0]; s1 += bfc[1];
        out[gw * 120 + td * 2] = s0;
        out[gw * 120 + td * 2 + 1] = s1;
        float* dn = g_decin[(td + 1) & 1];
        dn[gw * 2] = s0;
        dn[gw * 2 + 1] = s1;
    }
}

// ------------------ launch ------------------
extern "C" void kernel_launch(void* const* d_in, const int* in_sizes, int n_in,
                              void* d_out, int out_size) {
    (void)in_sizes; (void)n_in; (void)out_size;
    const float* x    = (const float*)d_in[0];
    const float* Wih0 = (const float*)d_in[1];
    const float* Whh0 = (const float*)d_in[2];
    const float* bih0 = (const float*)d_in[3];
    const float* bhh0 = (const float*)d_in[4];
    const float* Wih1 = (const float*)d_in[5];
    const float* Whh1 = (const float*)d_in[6];
    const float* bih1 = (const float*)d_in[7];
    const float* bhh1 = (const float*)d_in[8];
    const float* Wihd = (const float*)d_in[9];
    const float* Whhd = (const float*)d_in[10];
    const float* bihd = (const float*)d_in[11];
    const float* bhhd = (const float*)d_in[12];
    const float* Wfc  = (const float*)d_in[13];
    const float* bfc  = (const float*)d_in[14];
    float* out = (float*)d_out;

    cudaFuncSetAttribute(gru_step<0>, cudaFuncAttributeMaxDynamicSharedMemorySize, SMEM_BYTES);
    cudaFuncSetAttribute(gru_step<1>, cudaFuncAttributeMaxDynamicSharedMemorySize, SMEM_BYTES);
    cudaFuncSetAttribute(gru_step<2>, cudaFuncAttributeMaxDynamicSharedMemorySize, SMEM_BYTES);

    prep_kernel<<<1024, 256>>>(Whh0, Wih1, Whh1, Whhd,
                               bih0, bhh0, bih1, bhh1, bihd, bhhd);
    init_kernel<<<2048, 256>>>(x);

    dim3 grid(32, 8);  // 4096/128 x 512/64
    for (int t = 0; t < TOBS; ++t) {
        gru_step<0><<<grid, 512, SMEM_BYTES>>>(t, x, Wih0);
        gru_step<1><<<grid, 512, SMEM_BYTES>>>(t, x, (const float*)nullptr);
    }
    for (int td = 0; td < TPRED; ++td) {
        gru_step<2><<<grid, 512, SMEM_BYTES>>>(td, nullptr, Wihd);
        fc_kernel<<<512, 256>>>(td, Wfc, bfc, out);
    }
}

// round 8
// speedup vs baseline: 1.5666x; 1.1365x over previous
#include <cuda_runtime.h>
#include <cuda_fp16.h>
#include <cstdint>

#define B_    4096
#define H_    512
#define TOBS  30
#define TPRED 60

// ------------------ device scratch (static, no runtime alloc) ------------------
__device__ float g_h0[2][B_ * H_];
__device__ float g_h1[2][B_ * H_];
__device__ float g_hd[2][B_ * H_];
// fp16 images of h (A operand for MMA)
__device__ __half g_h0h[2][B_ * H_];
__device__ __half g_h1h[2][B_ * H_];
__device__ __half g_hdh[2][B_ * H_];
__device__ float g_decin[2][B_ * 2];
// packed fp16 fragment-interleaved weights:
// [kb16<32][g<3][jb<64][lane<32][v<2] u32 = pack(W[row][k0], W[row][k0+1])
// row = g*512 + jb*8 + lane/4, k0 = kb16*16 + 2*(lane%4) + 8*v
__device__ uint32_t g_Wp[4][393216];   // {W_hh0, W_ih1, W_hh1, W_hhd}
// combined bias table per layer: [j][4] = {bih_r+bhh_r, bih_z+bhh_z, bih_n, bhh_n}
__device__ float g_b4[3][H_ * 4];

// smem: 3-stage pipeline. A buf = 128 x 72 halves = 18432B; B buf = 96 x 256B = 24576B
#define SMA_BYTES 18432
#define SMB_BYTES 24576
#define SMB_OFF   (3 * SMA_BYTES)                     // 55296
#define SMEM_BYTES (3 * (SMA_BYTES + SMB_BYTES))      // 129024

// ------------------ helpers ------------------
__device__ __forceinline__ void mma16(float c[4], uint32_t a0, uint32_t a1, uint32_t a2,
                                      uint32_t a3, uint32_t b0, uint32_t b1) {
    asm volatile(
        "mma.sync.aligned.m16n8k16.row.col.f32.f16.f16.f32 "
        "{%0,%1,%2,%3},{%4,%5,%6,%7},{%8,%9},{%0,%1,%2,%3};"
        : "+f"(c[0]), "+f"(c[1]), "+f"(c[2]), "+f"(c[3])
        : "r"(a0), "r"(a1), "r"(a2), "r"(a3), "r"(b0), "r"(b1));
}
__device__ __forceinline__ void ldsm4(uint32_t a[4], uint32_t addr) {
    asm volatile("ldmatrix.sync.aligned.m8n8.x4.shared.b16 {%0,%1,%2,%3}, [%4];"
                 : "=r"(a[0]), "=r"(a[1]), "=r"(a[2]), "=r"(a[3]) : "r"(addr));
}
__device__ __forceinline__ void cpasync16(uint32_t dst, const void* src) {
    asm volatile("cp.async.cg.shared.global [%0], [%1], 16;" :: "r"(dst), "l"(src));
}
__device__ __forceinline__ float sigf(float v) { return 1.0f / (1.0f + __expf(-v)); }

// ------------------ prep: pack fp16 weights + combined biases ------------------
__global__ void prep_kernel(const float* __restrict__ Whh0, const float* __restrict__ Wih1,
                            const float* __restrict__ Whh1, const float* __restrict__ Whhd,
                            const float* __restrict__ bih0, const float* __restrict__ bhh0,
                            const float* __restrict__ bih1, const float* __restrict__ bhh1,
                            const float* __restrict__ bihd, const float* __restrict__ bhhd) {
    const int NW = 4 * 393216;
    const int total = NW + 3 * 2048;
    for (int idx = blockIdx.x * blockDim.x + threadIdx.x; idx < total;
         idx += gridDim.x * blockDim.x) {
        if (idx < NW) {
            int mat = idx / 393216, o = idx % 393216;
            int kb = o / 12288, rem = o % 12288;
            int g = rem / 4096, rem2 = rem % 4096;
            int jb = rem2 / 64, l2 = rem2 % 64;
            int lane = l2 >> 1, v = l2 & 1;
            int row = g * 512 + jb * 8 + (lane >> 2);
            int k0 = kb * 16 + 2 * (lane & 3) + 8 * v;
            const float* Wsrc = (mat == 0) ? Whh0 : (mat == 1) ? Wih1 : (mat == 2) ? Whh1 : Whhd;
            __half2 hv = __floats2half2_rn(Wsrc[row * 512 + k0], Wsrc[row * 512 + k0 + 1]);
            g_Wp[mat][o] = *reinterpret_cast<uint32_t*>(&hv);
        } else {
            int r = idx - NW;
            int l = r / 2048, rem = r % 2048;
            int j = rem >> 2, s = rem & 3;
            const float* bi = (l == 0) ? bih0 : (l == 1) ? bih1 : bihd;
            const float* bh = (l == 0) ? bhh0 : (l == 1) ? bhh1 : bhhd;
            float v;
            if (s == 0)      v = bi[j] + bh[j];
            else if (s == 1) v = bi[512 + j] + bh[512 + j];
            else if (s == 2) v = bi[1024 + j];
            else             v = bh[1024 + j];
            g_b4[l][j * 4 + s] = v;
        }
    }
}

__global__ void init_kernel(const float* __restrict__ x) {
    int idx0 = blockIdx.x * blockDim.x + threadIdx.x;
    for (int i = idx0; i < B_ * H_; i += gridDim.x * blockDim.x) {
        g_h0[0][i] = 0.0f;  g_h1[0][i] = 0.0f;
        g_h0h[0][i] = __float2half(0.0f);
        g_h1h[0][i] = __float2half(0.0f);
    }
    if (idx0 < B_ * 2) {
        int m = idx0 >> 1, o = idx0 & 1;
        g_decin[0][idx0] = x[m * 120 + 116 + o];  // x[m][29][o]
    }
}

// ------------------ fused GRU step: fp16 m16n8k16, 3-stage pipeline, LDSM A ------------------
// MODE 0: layer0 (x K=4 scalar ih, tensor hh). MODE 1: layer1 (tensor ih + hh, 2 passes).
// MODE 2: decoder (decin K=2 scalar ih, tensor hh).
template <int MODE>
__global__ void __launch_bounds__(512, 1)
gru_step(int t, const float* __restrict__ x, const float* __restrict__ Wraw) {
    extern __shared__ char smem[];
    uint32_t sb = (uint32_t)__cvta_generic_to_shared(smem);
    const int tid = threadIdx.x, lane = tid & 31, w = tid >> 5;
    const int wm = w & 3, wn = w >> 2;            // 4 M-warps x 4 N-warps
    const int m0 = blockIdx.x * 128, n0 = blockIdx.y * 64;
    const int jb_base = blockIdx.y * 8;

    const __half *Aimg0, *Aimg1 = nullptr;
    const uint32_t *Wp0, *Wp1 = nullptr;
    const float *hin, *b4p, *xsm = nullptr;
    float* hout;
    __half* himg;
    if constexpr (MODE == 0) {
        Aimg0 = g_h0h[t & 1]; Wp0 = g_Wp[0];
        hin = g_h0[t & 1]; hout = g_h0[(t + 1) & 1]; himg = g_h0h[(t + 1) & 1];
        b4p = g_b4[0];
    } else if constexpr (MODE == 1) {
        Aimg0 = g_h0h[(t + 1) & 1]; Wp0 = g_Wp[1];   // gi pass (x = new h0)
        Aimg1 = g_h1h[t & 1];       Wp1 = g_Wp[2];   // gh pass
        hin = g_h1[t & 1]; hout = g_h1[(t + 1) & 1]; himg = g_h1h[(t + 1) & 1];
        b4p = g_b4[1];
    } else {
        Aimg0 = (t == 0) ? g_h1h[0] : g_hdh[t & 1]; Wp0 = g_Wp[3];
        hin = (t == 0) ? g_h1[0] : g_hd[t & 1];
        hout = g_hd[(t + 1) & 1]; himg = g_hdh[(t + 1) & 1];
        b4p = g_b4[2]; xsm = g_decin[t & 1];
    }

    constexpr int SETS = (MODE == 1) ? 4 : 3;
    float acc[SETS][2][2][4];
#pragma unroll
    for (int s = 0; s < SETS; ++s)
#pragma unroll
        for (int mf = 0; mf < 2; ++mf)
#pragma unroll
            for (int nf = 0; nf < 2; ++nf)
#pragma unroll
                for (int q = 0; q < 4; ++q) acc[s][mf][nf][q] = 0.0f;

    // LDSM lane address offset within A buffer (x4: t0 rows0-7,k0-7; t1 rows8-15; t2 k8-15; t3)
    const int laneRow = (lane & 7) + ((lane >> 3) & 1) * 8;
    const int laneCol = (lane >> 4) * 8;
    const uint32_t aoff = (uint32_t)(((wm * 32 + laneRow) * 72 + laneCol) * 2);

    // chunk loader: A 128x64 fp16 (pitch 72 halves) + B 96 fragment-blocks of 256B
    auto load_chunk = [&](int cg) {
        const int b = cg % 3, pass = cg >> 3, c = cg & 7;
        const __half* A = (MODE == 1 && pass) ? Aimg1 : Aimg0;
        const uint32_t* W = (MODE == 1 && pass) ? Wp1 : Wp0;
        const uint32_t abase = sb + b * SMA_BYTES;
        const uint32_t bbase = sb + SMB_OFF + b * SMB_BYTES;
#pragma unroll
        for (int i = 0; i < 2; ++i) {
            int u = tid + i * 512;
            int row = u >> 3, c8 = (u & 7) << 3;
            cpasync16(abase + (uint32_t)((row * 72 + c8) * 2),
                      A + (m0 + row) * 512 + c * 64 + c8);
        }
#pragma unroll
        for (int i = 0; i < 3; ++i) {
            int u = tid + i * 512;
            int blk = u >> 4, q = u & 15;
            int ks = blk / 24, r24 = blk % 24;
            int g = r24 >> 3, jb = r24 & 7;
            cpasync16(bbase + (uint32_t)(blk * 256 + q * 16),
                      W + (c * 4 + ks) * 12288 + g * 4096 + (jb_base + jb) * 64 + q * 4);
        }
        asm volatile("cp.async.commit_group;" ::: "memory");
    };

    constexpr int NCH = (MODE == 1) ? 16 : 8;
    load_chunk(0);
    load_chunk(1);
    for (int cg = 0; cg < NCH; ++cg) {
        if (cg + 1 < NCH)
            asm volatile("cp.async.wait_group 1;" ::: "memory");
        else
            asm volatile("cp.async.wait_group 0;" ::: "memory");
        __syncthreads();
        if (cg + 2 < NCH) load_chunk(cg + 2);
        const int b = cg % 3, pass = cg >> 3;
        const uint32_t abase = sb + b * SMA_BYTES;
        const uint32_t* sB = reinterpret_cast<const uint32_t*>(smem + SMB_OFF + b * SMB_BYTES);
#pragma unroll
        for (int ks = 0; ks < 4; ++ks) {   // 4 x k16 per 64-col chunk
            uint32_t a[2][4];
            ldsm4(a[0], abase + aoff + ks * 32);
            ldsm4(a[1], abase + aoff + 2304 + ks * 32);   // mf=1: +16 rows * 144B
            const uint32_t* bp = sB + (ks * 24) * 64 + lane * 2;
#pragma unroll
            for (int g = 0; g < 3; ++g) {
                const int s = (g < 2) ? g : ((MODE == 1) ? (2 + pass) : 2);
#pragma unroll
                for (int nf = 0; nf < 2; ++nf) {
                    const uint2 bv = *reinterpret_cast<const uint2*>(
                        bp + (g * 8 + wn * 2 + nf) * 64);
                    mma16(acc[s][0][nf], a[0][0], a[0][1], a[0][2], a[0][3], bv.x, bv.y);
                    mma16(acc[s][1][nf], a[1][0], a[1][1], a[1][2], a[1][3], bv.x, bv.y);
                }
            }
        }
    }

    // ------------- epilogue: gates + h update -------------
#pragma unroll
    for (int mf = 0; mf < 2; ++mf) {
#pragma unroll
        for (int rr = 0; rr < 2; ++rr) {
            int m = m0 + wm * 32 + mf * 16 + rr * 8 + (lane >> 2);
            float4 xr = make_float4(0.f, 0.f, 0.f, 0.f);
            float2 x2 = make_float2(0.f, 0.f);
            if constexpr (MODE == 0) xr = *reinterpret_cast<const float4*>(&x[m * 120 + t * 4]);
            if constexpr (MODE == 2) x2 = *reinterpret_cast<const float2*>(&xsm[m * 2]);
#pragma unroll
            for (int nf = 0; nf < 2; ++nf) {
                int j = n0 + wn * 16 + nf * 8 + (lane & 3) * 2;
                float2 ho = *reinterpret_cast<const float2*>(&hin[m * 512 + j]);
                float hnew[2];
#pragma unroll
                for (int cc = 0; cc < 2; ++cc) {
                    int jj = j + cc;
                    float4 bb = *reinterpret_cast<const float4*>(&b4p[jj * 4]);
                    int q = rr * 2 + cc;
                    float vr = acc[0][mf][nf][q];
                    float vz = acc[1][mf][nf][q];
                    float gir = 0.f, giz = 0.f, gin = 0.f;
                    if constexpr (MODE == 0) {
                        float4 wr = *reinterpret_cast<const float4*>(&Wraw[jj * 4]);
                        float4 wz = *reinterpret_cast<const float4*>(&Wraw[(jj + 512) * 4]);
                        float4 wn4 = *reinterpret_cast<const float4*>(&Wraw[(jj + 1024) * 4]);
                        gir = xr.x * wr.x + xr.y * wr.y + xr.z * wr.z + xr.w * wr.w;
                        giz = xr.x * wz.x + xr.y * wz.y + xr.z * wz.z + xr.w * wz.w;
                        gin = xr.x * wn4.x + xr.y * wn4.y + xr.z * wn4.z + xr.w * wn4.w;
                    } else if constexpr (MODE == 2) {
                        float2 wr = *reinterpret_cast<const float2*>(&Wraw[jj * 2]);
                        float2 wz = *reinterpret_cast<const float2*>(&Wraw[(jj + 512) * 2]);
                        float2 wn2 = *reinterpret_cast<const float2*>(&Wraw[(jj + 1024) * 2]);
                        gir = x2.x * wr.x + x2.y * wr.y;
                        giz = x2.x * wz.x + x2.y * wz.y;
                        gin = x2.x * wn2.x + x2.y * wn2.y;
                    }
                    float rg = sigf(vr + gir + bb.x);
                    float zg = sigf(vz + giz + bb.y);
                    float in_term, hn_term;
                    if constexpr (MODE == 1) {
                        in_term = acc[2][mf][nf][q] + bb.z;
                        hn_term = acc[3][mf][nf][q] + bb.w;
                    } else {
                        in_term = gin + bb.z;
                        hn_term = acc[2][mf][nf][q] + bb.w;
                    }
                    float ng = tanhf(in_term + rg * hn_term);
                    float hprev = cc ? ho.y : ho.x;
                    hnew[cc] = (1.0f - zg) * ng + zg * hprev;
                }
                *reinterpret_cast<float2*>(&hout[m * 512 + j]) = make_float2(hnew[0], hnew[1]);
                __half2 hh = __floats2half2_rn(hnew[0], hnew[1]);
                *reinterpret_cast<__half2*>(&himg[m * 512 + j]) = hh;
            }
        }
    }
}

// ------------------ decoder FC: pred = h @ W_fc.T + b_fc; feed back ------------------
__global__ void fc_kernel(int td, const float* __restrict__ Wfc, const float* __restrict__ bfc,
                          float* __restrict__ out) {
    int gw = (blockIdx.x * blockDim.x + threadIdx.x) >> 5;  // one warp per batch row
    int lane = threadIdx.x & 31;
    if (gw >= B_) return;
    const float* h = g_hd[(td + 1) & 1] + gw * 512;
    float s0 = 0.f, s1 = 0.f;
#pragma unroll
    for (int i = 0; i < 16; ++i) {
        float hv = h[lane + 32 * i];
        s0 += hv * Wfc[lane + 32 * i];
        s1 += hv * Wfc[512 + lane + 32 * i];
    }
#pragma unroll
    for (int o = 16; o; o >>= 1) {
        s0 += __shfl_xor_sync(0xffffffffu, s0, o);
        s1 += __shfl_xor_sync(0xffffffffu, s1, o);
    }
    if (lane == 0) {
        s0 += bfc[0]; s1 += bfc[1];
        out[gw * 120 + td * 2] = s0;
        out[gw * 120 + td * 2 + 1] = s1;
        float* dn = g_decin[(td + 1) & 1];
        dn[gw * 2] = s0;
        dn[gw * 2 + 1] = s1;
    }
}

// ------------------ launch ------------------
extern "C" void kernel_launch(void* const* d_in, const int* in_sizes, int n_in,
                              void* d_out, int out_size) {
    (void)in_sizes; (void)n_in; (void)out_size;
    const float* x    = (const float*)d_in[0];
    const float* Wih0 = (const float*)d_in[1];
    const float* Whh0 = (const float*)d_in[2];
    const float* bih0 = (const float*)d_in[3];
    const float* bhh0 = (const float*)d_in[4];
    const float* Wih1 = (const float*)d_in[5];
    const float* Whh1 = (const float*)d_in[6];
    const float* bih1 = (const float*)d_in[7];
    const float* bhh1 = (const float*)d_in[8];
    const float* Wihd = (const float*)d_in[9];
    const float* Whhd = (const float*)d_in[10];
    const float* bihd = (const float*)d_in[11];
    const float* bhhd = (const float*)d_in[12];
    const float* Wfc  = (const float*)d_in[13];
    const float* bfc  = (const float*)d_in[14];
    float* out = (float*)d_out;

    cudaFuncSetAttribute(gru_step<0>, cudaFuncAttributeMaxDynamicSharedMemorySize, SMEM_BYTES);
    cudaFuncSetAttribute(gru_step<1>, cudaFuncAttributeMaxDynamicSharedMemorySize, SMEM_BYTES);
    cudaFuncSetAttribute(gru_step<2>, cudaFuncAttributeMaxDynamicSharedMemorySize, SMEM_BYTES);

    prep_kernel<<<1024, 256>>>(Whh0, Wih1, Whh1, Whhd,
                               bih0, bhh0, bih1, bhh1, bihd, bhhd);
    init_kernel<<<2048, 256>>>(x);

    dim3 grid(32, 8);  // 4096/128 x 512/64
    for (int t = 0; t < TOBS; ++t) {
        gru_step<0><<<grid, 512, SMEM_BYTES>>>(t, x, Wih0);
        gru_step<1><<<grid, 512, SMEM_BYTES>>>(t, x, (const float*)nullptr);
    }
    for (int td = 0; td < TPRED; ++td) {
        gru_step<2><<<grid, 512, SMEM_BYTES>>>(td, nullptr, Wihd);
        fc_kernel<<<512, 256>>>(td, Wfc, bfc, out);
    }
}

// round 9
// speedup vs baseline: 1.6223x; 1.0356x over previous
#include <cuda_runtime.h>
#include <cuda_fp16.h>
#include <cstdint>

#define B_    4096
#define H_    512
#define TOBS  30
#define TPRED 60

// ------------------ device scratch (static, no runtime alloc) ------------------
__device__ float g_h0[2][B_ * H_];
__device__ float g_h1[2][B_ * H_];
__device__ float g_hd[2][B_ * H_];
// fp16 images of h (A operand for MMA)
__device__ __half g_h0h[2][B_ * H_];
__device__ __half g_h1h[2][B_ * H_];
__device__ __half g_hdh[2][B_ * H_];
__device__ float g_decin[2][B_ * 2];
// packed fp16 weights for LDS.128 reads:
// u32 flat index r = ((kb*3+g)*32 + jb2)*128 + lane*4 + q,  q = half*2 + v
// jb = jb2*2 + (q>>1), v = q&1, row = g*512 + jb*8 + lane/4,
// k0 = kb*16 + 2*(lane%4) + 8*v ; u32 = pack_half2(W[row][k0], W[row][k0+1])
__device__ uint32_t g_Wp[4][393216];   // {W_hh0, W_ih1, W_hh1, W_hhd}
// combined bias table per layer: [j][4] = {bih_r+bhh_r, bih_z+bhh_z, bih_n, bhh_n}
__device__ float g_b4[3][H_ * 4];

// smem: 3-stage pipeline. A buf = 128 x 72 halves = 18432B; B buf = 24 x 512B = 12288B
#define SMA_BYTES 18432
#define SMB_BYTES 12288
#define SMB_OFF   (3 * SMA_BYTES)                     // 55296
#define SMEM_BYTES (3 * (SMA_BYTES + SMB_BYTES))      // 92160

// ------------------ helpers ------------------
__device__ __forceinline__ void mma16(float c[4], uint32_t a0, uint32_t a1, uint32_t a2,
                                      uint32_t a3, uint32_t b0, uint32_t b1) {
    asm volatile(
        "mma.sync.aligned.m16n8k16.row.col.f32.f16.f16.f32 "
        "{%0,%1,%2,%3},{%4,%5,%6,%7},{%8,%9},{%0,%1,%2,%3};"
        : "+f"(c[0]), "+f"(c[1]), "+f"(c[2]), "+f"(c[3])
        : "r"(a0), "r"(a1), "r"(a2), "r"(a3), "r"(b0), "r"(b1));
}
__device__ __forceinline__ void ldsm4(uint32_t a[4], uint32_t addr) {
    asm volatile("ldmatrix.sync.aligned.m8n8.x4.shared.b16 {%0,%1,%2,%3}, [%4];"
                 : "=r"(a[0]), "=r"(a[1]), "=r"(a[2]), "=r"(a[3]) : "r"(addr));
}
__device__ __forceinline__ void cpasync16(uint32_t dst, const void* src) {
    asm volatile("cp.async.cg.shared.global [%0], [%1], 16;" :: "r"(dst), "l"(src));
}
__device__ __forceinline__ float sigf(float v) { return 1.0f / (1.0f + __expf(-v)); }

// ------------------ prep: pack fp16 weights + combined biases ------------------
__global__ void prep_kernel(const float* __restrict__ Whh0, const float* __restrict__ Wih1,
                            const float* __restrict__ Whh1, const float* __restrict__ Whhd,
                            const float* __restrict__ bih0, const float* __restrict__ bhh0,
                            const float* __restrict__ bih1, const float* __restrict__ bhh1,
                            const float* __restrict__ bihd, const float* __restrict__ bhhd) {
    const int NW = 4 * 393216;
    const int total = NW + 3 * 2048;
    for (int idx = blockIdx.x * blockDim.x + threadIdx.x; idx < total;
         idx += gridDim.x * blockDim.x) {
        if (idx < NW) {
            int mat = idx / 393216, r = idx % 393216;
            int kb = r / 12288, r2 = r % 12288;
            int g = r2 / 4096, r3 = r2 % 4096;
            int jb2 = r3 / 128, r4 = r3 % 128;
            int lane = r4 >> 2, q = r4 & 3;
            int jb = jb2 * 2 + (q >> 1), v = q & 1;
            int row = g * 512 + jb * 8 + (lane >> 2);
            int k0 = kb * 16 + 2 * (lane & 3) + 8 * v;
            const float* Wsrc = (mat == 0) ? Whh0 : (mat == 1) ? Wih1 : (mat == 2) ? Whh1 : Whhd;
            __half2 hv = __floats2half2_rn(Wsrc[row * 512 + k0], Wsrc[row * 512 + k0 + 1]);
            g_Wp[mat][r] = *reinterpret_cast<uint32_t*>(&hv);
        } else {
            int r = idx - NW;
            int l = r / 2048, rem = r % 2048;
            int j = rem >> 2, s = rem & 3;
            const float* bi = (l == 0) ? bih0 : (l == 1) ? bih1 : bihd;
            const float* bh = (l == 0) ? bhh0 : (l == 1) ? bhh1 : bhhd;
            float v;
            if (s == 0)      v = bi[j] + bh[j];
            else if (s == 1) v = bi[512 + j] + bh[512 + j];
            else if (s == 2) v = bi[1024 + j];
            else             v = bh[1024 + j];
            g_b4[l][j * 4 + s] = v;
        }
    }
}

__global__ void init_kernel(const float* __restrict__ x) {
    int idx0 = blockIdx.x * blockDim.x + threadIdx.x;
    for (int i = idx0; i < B_ * H_; i += gridDim.x * blockDim.x) {
        g_h0[0][i] = 0.0f;  g_h1[0][i] = 0.0f;
        g_h0h[0][i] = __float2half(0.0f);
        g_h1h[0][i] = __float2half(0.0f);
    }
    if (idx0 < B_ * 2) {
        int m = idx0 >> 1, o = idx0 & 1;
        g_decin[0][idx0] = x[m * 120 + 116 + o];  // x[m][29][o]
    }
}

// ------------------ fused GRU step: 256 thr, 2 CTAs/SM, tile 128x32 ------------------
// MODE 0: layer0 (x K=4 scalar ih, tensor hh). MODE 1: layer1 (tensor ih + hh, 2 passes).
// MODE 2: decoder (decin K=2 scalar ih, tensor hh).
template <int MODE>
__global__ void __launch_bounds__(256, 2)
gru_step(int t, const float* __restrict__ x, const float* __restrict__ Wraw) {
    extern __shared__ char smem[];
    uint32_t sb = (uint32_t)__cvta_generic_to_shared(smem);
    const int tid = threadIdx.x, lane = tid & 31, w = tid >> 5;
    const int wm = w & 3, wn = w >> 2;            // 4 M-warps x 2 N-warps
    const int m0 = blockIdx.x * 128;
    const int y = blockIdx.y;                     // 16 n-slices of 32 cols
    const int n0 = y * 32;

    const __half *Aimg0, *Aimg1 = nullptr;
    const uint32_t *Wp0, *Wp1 = nullptr;
    const float *hin, *b4p, *xsm = nullptr;
    float* hout;
    __half* himg;
    if constexpr (MODE == 0) {
        Aimg0 = g_h0h[t & 1]; Wp0 = g_Wp[0];
        hin = g_h0[t & 1]; hout = g_h0[(t + 1) & 1]; himg = g_h0h[(t + 1) & 1];
        b4p = g_b4[0];
    } else if constexpr (MODE == 1) {
        Aimg0 = g_h0h[(t + 1) & 1]; Wp0 = g_Wp[1];   // gi pass (x = new h0)
        Aimg1 = g_h1h[t & 1];       Wp1 = g_Wp[2];   // gh pass
        hin = g_h1[t & 1]; hout = g_h1[(t + 1) & 1]; himg = g_h1h[(t + 1) & 1];
        b4p = g_b4[1];
    } else {
        Aimg0 = (t == 0) ? g_h1h[0] : g_hdh[t & 1]; Wp0 = g_Wp[3];
        hin = (t == 0) ? g_h1[0] : g_hd[t & 1];
        hout = g_hd[(t + 1) & 1]; himg = g_hdh[(t + 1) & 1];
        b4p = g_b4[2]; xsm = g_decin[t & 1];
    }

    constexpr int SETS = (MODE == 1) ? 4 : 3;
    float acc[SETS][2][2][4];
#pragma unroll
    for (int s = 0; s < SETS; ++s)
#pragma unroll
        for (int mf = 0; mf < 2; ++mf)
#pragma unroll
            for (int nf = 0; nf < 2; ++nf)
#pragma unroll
                for (int q = 0; q < 4; ++q) acc[s][mf][nf][q] = 0.0f;

    // LDSM lane address offset within A buffer
    const int laneRow = (lane & 7) + ((lane >> 3) & 1) * 8;
    const int laneCol = (lane >> 4) * 8;
    const uint32_t aoff = (uint32_t)(((wm * 32 + laneRow) * 72 + laneCol) * 2);

    // chunk loader: A 128x64 fp16 (pitch 72 halves) + B 24 blocks x 512B
    auto load_chunk = [&](int cg) {
        const int b = cg % 3, pass = cg >> 3, c = cg & 7;
        const __half* A = (MODE == 1 && pass) ? Aimg1 : Aimg0;
        const uint32_t* W = (MODE == 1 && pass) ? Wp1 : Wp0;
        const uint32_t abase = sb + b * SMA_BYTES;
        const uint32_t bbase = sb + SMB_OFF + b * SMB_BYTES;
#pragma unroll
        for (int i = 0; i < 4; ++i) {
            int u = tid + i * 256;
            int row = u >> 3, c8 = (u & 7) << 3;
            cpasync16(abase + (uint32_t)((row * 72 + c8) * 2),
                      A + (m0 + row) * 512 + c * 64 + c8);
        }
#pragma unroll
        for (int i = 0; i < 3; ++i) {
            int u = tid + i * 256;            // 0..767
            int blk = u >> 5, q = u & 31;     // 24 blocks x 32 uint4
            int ks = blk / 6, r6 = blk % 6;
            int g = r6 >> 1, p = r6 & 1;
            int jb2 = y * 2 + p;
            cpasync16(bbase + (uint32_t)(blk * 512 + q * 16),
                      W + ((((c * 4 + ks) * 3 + g) * 32 + jb2) * 32 + q) * 4);
        }
        asm volatile("cp.async.commit_group;" ::: "memory");
    };

    constexpr int NCH = (MODE == 1) ? 16 : 8;
    load_chunk(0);
    load_chunk(1);
    for (int cg = 0; cg < NCH; ++cg) {
        if (cg + 1 < NCH)
            asm volatile("cp.async.wait_group 1;" ::: "memory");
        else
            asm volatile("cp.async.wait_group 0;" ::: "memory");
        __syncthreads();
        if (cg + 2 < NCH) load_chunk(cg + 2);
        const int b = cg % 3, pass = cg >> 3;
        const uint32_t abase = sb + b * SMA_BYTES;
        const uint4* sB = reinterpret_cast<const uint4*>(smem + SMB_OFF + b * SMB_BYTES);
#pragma unroll
        for (int ks = 0; ks < 4; ++ks) {   // 4 x k16 per 64-col chunk
            uint32_t a[2][4];
            ldsm4(a[0], abase + aoff + ks * 32);
            ldsm4(a[1], abase + aoff + 2304 + ks * 32);   // mf=1: +16 rows * 144B
#pragma unroll
            for (int g = 0; g < 3; ++g) {
                const int s = (g < 2) ? g : ((MODE == 1) ? (2 + pass) : 2);
                const uint4 bv = sB[((ks * 3 + g) * 2 + wn) * 32 + lane];
                mma16(acc[s][0][0], a[0][0], a[0][1], a[0][2], a[0][3], bv.x, bv.y);
                mma16(acc[s][1][0], a[1][0], a[1][1], a[1][2], a[1][3], bv.x, bv.y);
                mma16(acc[s][0][1], a[0][0], a[0][1], a[0][2], a[0][3], bv.z, bv.w);
                mma16(acc[s][1][1], a[1][0], a[1][1], a[1][2], a[1][3], bv.z, bv.w);
            }
        }
    }

    // ------------- epilogue: gates + h update -------------
#pragma unroll
    for (int mf = 0; mf < 2; ++mf) {
#pragma unroll
        for (int rr = 0; rr < 2; ++rr) {
            int m = m0 + wm * 32 + mf * 16 + rr * 8 + (lane >> 2);
            float4 xr = make_float4(0.f, 0.f, 0.f, 0.f);
            float2 x2 = make_float2(0.f, 0.f);
            if constexpr (MODE == 0) xr = *reinterpret_cast<const float4*>(&x[m * 120 + t * 4]);
            if constexpr (MODE == 2) x2 = *reinterpret_cast<const float2*>(&xsm[m * 2]);
#pragma unroll
            for (int nf = 0; nf < 2; ++nf) {
                int j = n0 + wn * 16 + nf * 8 + (lane & 3) * 2;
                float2 ho = *reinterpret_cast<const float2*>(&hin[m * 512 + j]);
                float hnew[2];
#pragma unroll
                for (int cc = 0; cc < 2; ++cc) {
                    int jj = j + cc;
                    float4 bb = *reinterpret_cast<const float4*>(&b4p[jj * 4]);
                    int q = rr * 2 + cc;
                    float vr = acc[0][mf][nf][q];
                    float vz = acc[1][mf][nf][q];
                    float gir = 0.f, giz = 0.f, gin = 0.f;
                    if constexpr (MODE == 0) {
                        float4 wr = *reinterpret_cast<const float4*>(&Wraw[jj * 4]);
                        float4 wz = *reinterpret_cast<const float4*>(&Wraw[(jj + 512) * 4]);
                        float4 wn4 = *reinterpret_cast<const float4*>(&Wraw[(jj + 1024) * 4]);
                        gir = xr.x * wr.x + xr.y * wr.y + xr.z * wr.z + xr.w * wr.w;
                        giz = xr.x * wz.x + xr.y * wz.y + xr.z * wz.z + xr.w * wz.w;
                        gin = xr.x * wn4.x + xr.y * wn4.y + xr.z * wn4.z + xr.w * wn4.w;
                    } else if constexpr (MODE == 2) {
                        float2 wr = *reinterpret_cast<const float2*>(&Wraw[jj * 2]);
                        float2 wz = *reinterpret_cast<const float2*>(&Wraw[(jj + 512) * 2]);
                        float2 wn2 = *reinterpret_cast<const float2*>(&Wraw[(jj + 1024) * 2]);
                        gir = x2.x * wr.x + x2.y * wr.y;
                        giz = x2.x * wz.x + x2.y * wz.y;
                        gin = x2.x * wn2.x + x2.y * wn2.y;
                    }
                    float rg = sigf(vr + gir + bb.x);
                    float zg = sigf(vz + giz + bb.y);
                    float in_term, hn_term;
                    if constexpr (MODE == 1) {
                        in_term = acc[2][mf][nf][q] + bb.z;
                        hn_term = acc[3][mf][nf][q] + bb.w;
                    } else {
                        in_term = gin + bb.z;
                        hn_term = acc[2][mf][nf][q] + bb.w;
                    }
                    float ng = tanhf(in_term + rg * hn_term);
                    float hprev = cc ? ho.y : ho.x;
                    hnew[cc] = (1.0f - zg) * ng + zg * hprev;
                }
                *reinterpret_cast<float2*>(&hout[m * 512 + j]) = make_float2(hnew[0], hnew[1]);
                __half2 hh = __floats2half2_rn(hnew[0], hnew[1]);
                *reinterpret_cast<__half2*>(&himg[m * 512 + j]) = hh;
            }
        }
    }
}

// ------------------ decoder FC: pred = h @ W_fc.T + b_fc; feed back ------------------
__global__ void fc_kernel(int td, const float* __restrict__ Wfc, const float* __restrict__ bfc,
                          float* __restrict__ out) {
    int gw = (blockIdx.x * blockDim.x + threadIdx.x) >> 5;  // one warp per batch row
    int lane = threadIdx.x & 31;
    if (gw >= B_) return;
    const float* h = g_hd[(td + 1) & 1] + gw * 512;
    float s0 = 0.f, s1 = 0.f;
#pragma unroll
    for (int i = 0; i < 16; ++i) {
        float hv = h[lane + 32 * i];
        s0 += hv * Wfc[lane + 32 * i];
        s1 += hv * Wfc[512 + lane + 32 * i];
    }
#pragma unroll
    for (int o = 16; o; o >>= 1) {
        s0 += __shfl_xor_sync(0xffffffffu, s0, o);
        s1 += __shfl_xor_sync(0xffffffffu, s1, o);
    }
    if (lane == 0) {
        s0 += bfc[0]; s1 += bfc[1];
        out[gw * 120 + td * 2] = s0;
        out[gw * 120 + td * 2 + 1] = s1;
        float* dn = g_decin[(td + 1) & 1];
        dn[gw * 2] = s0;
        dn[gw * 2 + 1] = s1;
    }
}

// ------------------ launch ------------------
extern "C" void kernel_launch(void* const* d_in, const int* in_sizes, int n_in,
                              void* d_out, int out_size) {
    (void)in_sizes; (void)n_in; (void)out_size;
    const float* x    = (const float*)d_in[0];
    const float* Wih0 = (const float*)d_in[1];
    const float* Whh0 = (const float*)d_in[2];
    const float* bih0 = (const float*)d_in[3];
    const float* bhh0 = (const float*)d_in[4];
    const float* Wih1 = (const float*)d_in[5];
    const float* Whh1 = (const float*)d_in[6];
    const float* bih1 = (const float*)d_in[7];
    const float* bhh1 = (const float*)d_in[8];
    const float* Wihd = (const float*)d_in[9];
    const float* Whhd = (const float*)d_in[10];
    const float* bihd = (const float*)d_in[11];
    const float* bhhd = (const float*)d_in[12];
    const float* Wfc  = (const float*)d_in[13];
    const float* bfc  = (const float*)d_in[14];
    float* out = (float*)d_out;

    cudaFuncSetAttribute(gru_step<0>, cudaFuncAttributeMaxDynamicSharedMemorySize, SMEM_BYTES);
    cudaFuncSetAttribute(gru_step<1>, cudaFuncAttributeMaxDynamicSharedMemorySize, SMEM_BYTES);
    cudaFuncSetAttribute(gru_step<2>, cudaFuncAttributeMaxDynamicSharedMemorySize, SMEM_BYTES);

    prep_kernel<<<1024, 256>>>(Whh0, Wih1, Whh1, Whhd,
                               bih0, bhh0, bih1, bhh1, bihd, bhhd);
    init_kernel<<<2048, 256>>>(x);

    dim3 grid(32, 16);  // 4096/128 x 512/32
    for (int t = 0; t < TOBS; ++t) {
        gru_step<0><<<grid, 256, SMEM_BYTES>>>(t, x, Wih0);
        gru_step<1><<<grid, 256, SMEM_BYTES>>>(t, x, (const float*)nullptr);
    }
    for (int td = 0; td < TPRED; ++td) {
        gru_step<2><<<grid, 256, SMEM_BYTES>>>(td, nullptr, Wihd);
        fc_kernel<<<512, 256>>>(td, Wfc, bfc, out);
    }
}